// round 7
// baseline (speedup 1.0000x reference)
#include <cuda_runtime.h>
#include <math.h>

// gelu_tanh(x) * gate with the identity 0.5*(1+tanh(y)) = e/(e+1), e = exp(2y).
// 2y*log2(e) = x*(1 + 0.044715 x^2) * K,  K = 2*sqrt(2/pi)*log2(e).
__device__ __forceinline__ float gelu_gated(float x, float gate) {
    const float A = 0.044715f;
    const float K = 2.3022082f;            // 2 * 0.7978845608 * 1.44269504
    float t = x * x;
    float u = fmaf(A, t, 1.0f);
    float w = (x * u) * K;                 // = 2*y*log2e
    w = fminf(w, 120.0f);                  // keep ex2 finite; ftz->0 on deep negative
    float e;
    asm("ex2.approx.ftz.f32 %0, %1;" : "=f"(e) : "f"(w));
    float d = e + 1.0f;
    float r;
    asm("rcp.approx.ftz.f32 %0, %1;" : "=f"(r) : "f"(d));
    return (x * gate) * (e * r);
}

// Single kernel: each thread computes the scalar gate (2 broadcast loads,
// amortized over 8 elements) then processes 2 float4s with front-batched loads.
__global__ __launch_bounds__(256) void gelu_main_kernel(const float4* __restrict__ x,
                                                        const float* __restrict__ log_alpha,
                                                        const float* __restrict__ log_sigma,
                                                        float4* __restrict__ out,
                                                        float surp,
                                                        int n4) {
    int base = (blockIdx.x * blockDim.x + threadIdx.x) * 2;

    // Front-batch the data loads so they are in flight while the gate math runs.
    bool full = (base + 1 < n4);
    bool tail = (base < n4);
    float4 v0, v1;
    if (full) {
        v0 = x[base];
        v1 = x[base + 1];
    } else if (tail) {
        v0 = x[base];
    }

    // Gate: broadcast scalar loads (L1-hit after the first warp), accurate path.
    float alpha = expf(__ldg(log_alpha));
    float sigma = expf(__ldg(log_sigma));
    float gate = 1.0f + alpha * tanhf(sigma * surp);

    if (full) {
        float4 o0, o1;
        o0.x = gelu_gated(v0.x, gate);
        o0.y = gelu_gated(v0.y, gate);
        o0.z = gelu_gated(v0.z, gate);
        o0.w = gelu_gated(v0.w, gate);
        o1.x = gelu_gated(v1.x, gate);
        o1.y = gelu_gated(v1.y, gate);
        o1.z = gelu_gated(v1.z, gate);
        o1.w = gelu_gated(v1.w, gate);
        out[base]     = o0;
        out[base + 1] = o1;
    } else if (tail) {
        float4 o0;
        o0.x = gelu_gated(v0.x, gate);
        o0.y = gelu_gated(v0.y, gate);
        o0.z = gelu_gated(v0.z, gate);
        o0.w = gelu_gated(v0.w, gate);
        out[base] = o0;
    }
}

extern "C" void kernel_launch(void* const* d_in, const int* in_sizes, int n_in,
                              void* d_out, int out_size) {
    const float* x         = (const float*)d_in[0];
    const float* log_alpha = (const float*)d_in[1];
    const float* log_sigma = (const float*)d_in[2];
    float* out = (float*)d_out;

    // surp is analytically N/(2(N-1)): double-argsort yields a permutation of
    // 0..N-1 in every column, so mean(2|rank/(N-1) - 0.5|) is data-independent.
    const int D = 4096;                    // feature dim (metadata: x is [4,2048,4096])
    long long total = (long long)in_sizes[0];
    long long N = total / D;               // 8192 token rows
    float surp = (float)((double)N / (2.0 * (double)(N - 1)));

    int n4 = out_size / 4;                 // 8388608 float4s
    int threads = 256;
    int vec_per_block = threads * 2;
    int blocks = (n4 + vec_per_block - 1) / vec_per_block;
    gelu_main_kernel<<<blocks, threads>>>((const float4*)x, log_alpha, log_sigma,
                                          (float4*)out, surp, n4);
}